// round 2
// baseline (speedup 1.0000x reference)
#include <cuda_runtime.h>
#include <math.h>

#define NN 40000
#define NE 640000
#define D 128
#define DC 512
#define NCLS 40
#define SCAN_NB ((NN + 255) / 256)   // 157

// ---------------- device scratch (static, allowed) ----------------
__device__ int   g_deg[NN];
__device__ float g_dinv[NN];
__device__ int   g_off[NN + 1];
__device__ int   g_pos[NN];
__device__ int   g_src[NE];
__device__ int   g_bsum[SCAN_NB];
__device__ __align__(16) float g_gbuf[NN * D];    // dinv-scaled hidden
__device__ __align__(16) float g_feat[NN * DC];   // [mean|add|min|max]
__device__ __align__(16) float g_x1[NN * D];      // layer output

// ---------------- small utilities ----------------
__device__ __forceinline__ int warp_iscan(int v) {
    #pragma unroll
    for (int d = 1; d < 32; d <<= 1) {
        int t = __shfl_up_sync(0xffffffffu, v, d);
        if ((threadIdx.x & 31) >= d) v += t;
    }
    return v;
}

// ---------------- graph preprocessing ----------------
__global__ void k_init() {
    int i = blockIdx.x * 256 + threadIdx.x;
    if (i < NN) g_deg[i] = 1;                       // self loop
}

__global__ void k_count(const int* __restrict__ ei) {
    int e = blockIdx.x * 256 + threadIdx.x;
    if (e < NE) atomicAdd(&g_deg[ei[NE + e]], 1);   // col = ei[E..2E)
}

__global__ void k_scan_a() {
    __shared__ int wsum[8];
    int i = blockIdx.x * 256 + threadIdx.x;
    int cnt = (i < NN) ? (g_deg[i] - 1) : 0;        // real in-edges only
    int inc = warp_iscan(cnt);
    int wid = threadIdx.x >> 5, lane = threadIdx.x & 31;
    if (lane == 31) wsum[wid] = inc;
    __syncthreads();
    if (wid == 0) {
        int v = (lane < 8) ? wsum[lane] : 0;
        v = warp_iscan(v);
        if (lane < 8) wsum[lane] = v;
    }
    __syncthreads();
    int base = wid ? wsum[wid - 1] : 0;
    if (i < NN) g_off[i] = base + inc - cnt;        // block-local exclusive
    if (threadIdx.x == 255) g_bsum[blockIdx.x] = base + inc;
}

__global__ void k_scan_b() {
    __shared__ int wsum[8];
    int t = threadIdx.x;
    int v = (t < SCAN_NB) ? g_bsum[t] : 0;
    int inc = warp_iscan(v);
    int wid = t >> 5, lane = t & 31;
    if (lane == 31) wsum[wid] = inc;
    __syncthreads();
    if (wid == 0) {
        int u = (lane < 8) ? wsum[lane] : 0;
        u = warp_iscan(u);
        if (lane < 8) wsum[lane] = u;
    }
    __syncthreads();
    int base = wid ? wsum[wid - 1] : 0;
    if (t < SCAN_NB) g_bsum[t] = base + inc - v;    // exclusive block offsets
}

__global__ void k_scan_c() {
    int i = blockIdx.x * 256 + threadIdx.x;
    if (i < NN) {
        int o = g_off[i] + g_bsum[i >> 8];
        g_off[i] = o;
        g_pos[i] = o;
        g_dinv[i] = rsqrtf((float)g_deg[i]);
    }
    if (i == 0) g_off[NN] = NE;
}

__global__ void k_fill(const int* __restrict__ ei) {
    int e = blockIdx.x * 256 + threadIdx.x;
    if (e < NE) {
        int c = ei[NE + e];
        int p = atomicAdd(&g_pos[c], 1);
        g_src[p] = ei[e];                            // row = ei[0..E)
    }
}

// ---------------- aggregation: warp per node (g_gbuf -> g_feat) ----------------
__device__ __forceinline__ void upd(float4& s, float4& mn, float4& mx, float4 u) {
    s.x += u.x; s.y += u.y; s.z += u.z; s.w += u.w;
    mn.x = fminf(mn.x, u.x); mn.y = fminf(mn.y, u.y);
    mn.z = fminf(mn.z, u.z); mn.w = fminf(mn.w, u.w);
    mx.x = fmaxf(mx.x, u.x); mx.y = fmaxf(mx.y, u.y);
    mx.z = fmaxf(mx.z, u.z); mx.w = fmaxf(mx.w, u.w);
}

__global__ void __launch_bounds__(256) k_aggregate() {
    int w = threadIdx.x >> 5, lane = threadIdx.x & 31;
    int c = blockIdx.x * 8 + w;
    const float4* gv = (const float4*)g_gbuf;
    float4 v = gv[c * 32 + lane];                    // self-loop message (g[c])
    float4 s = v, mn = v, mx = v;
    int e0 = g_off[c], e1 = g_off[c + 1];
    int j = e0;
    for (; j + 2 <= e1; j += 2) {                    // unroll 2 for MLP
        int r0 = __ldg(&g_src[j]);
        int r1 = __ldg(&g_src[j + 1]);
        float4 u0 = __ldg(&gv[r0 * 32 + lane]);
        float4 u1 = __ldg(&gv[r1 * 32 + lane]);
        upd(s, mn, mx, u0);
        upd(s, mn, mx, u1);
    }
    if (j < e1) {
        int r = __ldg(&g_src[j]);
        upd(s, mn, mx, __ldg(&gv[r * 32 + lane]));
    }
    float di  = g_dinv[c];
    float rdg = 1.0f / (float)g_deg[c];
    float4* fv = (float4*)g_feat;
    int b = c * (DC / 4);
    float4 ad  = make_float4(di * s.x,  di * s.y,  di * s.z,  di * s.w);
    fv[b + lane]      = make_float4(ad.x * rdg, ad.y * rdg, ad.z * rdg, ad.w * rdg); // mean
    fv[b + 32 + lane] = ad;                                                          // add
    fv[b + 64 + lane] = make_float4(di * mn.x, di * mn.y, di * mn.z, di * mn.w);     // min
    fv[b + 96 + lane] = make_float4(di * mx.x, di * mx.y, di * mx.z, di * mx.w);     // max
}

// ---------------- SGEMM: C[M,128] = A[M,K] @ B[128,K]^T, fused epilogue ----------------
// ASRC: 0 = external A param, 1 = g_feat, 2 = g_x1
// CDST: 0 = g_gbuf,           1 = g_x1
// EPI==1: C[m][n] = g_dinv[m] * acc        (dinv row-scale -> g buffer)
// EPI==2: C[m][n] = relu(acc + bias[n])    (bias + relu -> layer output)
template <int K, int EPI, int ASRC, int CDST>
__global__ void __launch_bounds__(256) k_sgemm(const float* __restrict__ Aext,
                                               const float* __restrict__ B,
                                               const float* __restrict__ bias_p) {
    const float* A = (ASRC == 0) ? Aext : (ASRC == 1 ? (const float*)g_feat
                                                     : (const float*)g_x1);
    float* C = (CDST == 0) ? g_gbuf : g_x1;

    __shared__ float As[16][132];
    __shared__ float Bs[16][132];
    const int tid = threadIdx.x;
    const int bm0 = blockIdx.x * 128;
    const int tm = (tid >> 4) << 3;       // 0..120 step 8
    const int tn = (tid & 15) << 3;       // 0..120 step 8
    const int lr = tid >> 1;              // 0..127 (A row / B row)
    const int lk = (tid & 1) << 3;        // 0 or 8

    float acc[8][8];
    #pragma unroll
    for (int i = 0; i < 8; i++)
        #pragma unroll
        for (int j = 0; j < 8; j++) acc[i][j] = 0.f;

    const bool arow = (bm0 + lr) < NN;
    const float* Ap = A + (size_t)(arow ? (bm0 + lr) : 0) * K + lk;
    const float* Bp = B + (size_t)lr * K + lk;

    for (int k0 = 0; k0 < K; k0 += 16) {
        float4 a0 = make_float4(0.f, 0.f, 0.f, 0.f), a1 = a0;
        if (arow) {
            a0 = *(const float4*)(Ap + k0);
            a1 = *(const float4*)(Ap + k0 + 4);
        }
        float4 b0 = *(const float4*)(Bp + k0);
        float4 b1 = *(const float4*)(Bp + k0 + 4);
        As[lk + 0][lr] = a0.x; As[lk + 1][lr] = a0.y;
        As[lk + 2][lr] = a0.z; As[lk + 3][lr] = a0.w;
        As[lk + 4][lr] = a1.x; As[lk + 5][lr] = a1.y;
        As[lk + 6][lr] = a1.z; As[lk + 7][lr] = a1.w;
        Bs[lk + 0][lr] = b0.x; Bs[lk + 1][lr] = b0.y;
        Bs[lk + 2][lr] = b0.z; Bs[lk + 3][lr] = b0.w;
        Bs[lk + 4][lr] = b1.x; Bs[lk + 5][lr] = b1.y;
        Bs[lk + 6][lr] = b1.z; Bs[lk + 7][lr] = b1.w;
        __syncthreads();
        #pragma unroll
        for (int k = 0; k < 16; k++) {
            float4 av0 = *(const float4*)&As[k][tm];
            float4 av1 = *(const float4*)&As[k][tm + 4];
            float4 bv0 = *(const float4*)&Bs[k][tn];
            float4 bv1 = *(const float4*)&Bs[k][tn + 4];
            float a[8] = {av0.x, av0.y, av0.z, av0.w, av1.x, av1.y, av1.z, av1.w};
            float b[8] = {bv0.x, bv0.y, bv0.z, bv0.w, bv1.x, bv1.y, bv1.z, bv1.w};
            #pragma unroll
            for (int i = 0; i < 8; i++)
                #pragma unroll
                for (int j = 0; j < 8; j++)
                    acc[i][j] = fmaf(a[i], b[j], acc[i][j]);
        }
        __syncthreads();
    }

    float bias[8];
    if (EPI == 2) {
        #pragma unroll
        for (int j = 0; j < 8; j++) bias[j] = bias_p[tn + j];
    }
    #pragma unroll
    for (int i = 0; i < 8; i++) {
        int row = bm0 + tm + i;
        if (row < NN) {
            float o[8];
            if (EPI == 1) {
                float di = g_dinv[row];
                #pragma unroll
                for (int j = 0; j < 8; j++) o[j] = di * acc[i][j];
            } else {
                #pragma unroll
                for (int j = 0; j < 8; j++) o[j] = fmaxf(acc[i][j] + bias[j], 0.f);
            }
            float4* cp = (float4*)&C[(size_t)row * 128 + tn];
            cp[0] = make_float4(o[0], o[1], o[2], o[3]);
            cp[1] = make_float4(o[4], o[5], o[6], o[7]);
        }
    }
}

// ---------------- classifier + log_softmax: warp per node (reads g_x1) ----------------
__global__ void __launch_bounds__(256) k_out(const float* __restrict__ W,
                                             const float* __restrict__ bias,
                                             float* __restrict__ out) {
    __shared__ float ws[NCLS * 129];
    __shared__ float xs[8][128];
    __shared__ float bs[NCLS];
    int tid = threadIdx.x;
    for (int i = tid; i < NCLS * D; i += 256) {
        int c = i >> 7, k = i & 127;
        ws[c * 129 + k] = W[i];
    }
    if (tid < NCLS) bs[tid] = bias[tid];
    int w = tid >> 5, lane = tid & 31;
    int node = blockIdx.x * 8 + w;
    #pragma unroll
    for (int q = 0; q < 4; q++)
        xs[w][lane + 32 * q] = g_x1[node * D + lane + 32 * q];
    __syncthreads();

    int c2 = 32 + (lane & 7);
    float acc0 = bs[lane];
    float acc1 = bs[c2];
    #pragma unroll 8
    for (int k = 0; k < D; k++) {
        float xv = xs[w][k];
        acc0 = fmaf(xv, ws[lane * 129 + k], acc0);
        acc1 = fmaf(xv, ws[c2 * 129 + k], acc1);
    }
    bool v1 = (lane < 8);
    float m = fmaxf(acc0, v1 ? acc1 : -1e30f);
    #pragma unroll
    for (int d = 16; d; d >>= 1) m = fmaxf(m, __shfl_xor_sync(0xffffffffu, m, d));
    float s = expf(acc0 - m) + (v1 ? expf(acc1 - m) : 0.f);
    #pragma unroll
    for (int d = 16; d; d >>= 1) s += __shfl_xor_sync(0xffffffffu, s, d);
    float lse = m + logf(s);
    out[node * NCLS + lane] = acc0 - lse;
    if (v1) out[node * NCLS + 32 + lane] = acc1 - lse;
}

// ---------------- launch ----------------
extern "C" void kernel_launch(void* const* d_in, const int* in_sizes, int n_in,
                              void* d_out, int out_size) {
    (void)in_sizes; (void)n_in; (void)out_size;
    const float* x    = (const float*)d_in[0];
    const int*   ei   = (const int*)d_in[1];
    const float* W0   = (const float*)d_in[2];
    const float* C0   = (const float*)d_in[3];
    const float* b0   = (const float*)d_in[4];
    const float* W1   = (const float*)d_in[5];
    const float* C1   = (const float*)d_in[6];
    const float* b1   = (const float*)d_in[7];
    const float* Wout = (const float*)d_in[8];
    const float* bout = (const float*)d_in[9];
    float* out = (float*)d_out;

    const int EB = (NE + 255) / 256;
    const int MT = (NN + 127) / 128;

    // build CSR-by-destination + degrees + dinv
    k_init  <<<SCAN_NB, 256>>>();
    k_count <<<EB, 256>>>(ei);
    k_scan_a<<<SCAN_NB, 256>>>();
    k_scan_b<<<1, 256>>>();
    k_scan_c<<<SCAN_NB, 256>>>();
    k_fill  <<<EB, 256>>>(ei);

    // layer 0: g = dinv*(x@W0^T); aggregate; x1 = relu(feat@C0^T + b0)
    k_sgemm<128, 1, 0, 0><<<MT, 256>>>(x, W0, nullptr);
    k_aggregate<<<NN / 8, 256>>>();
    k_sgemm<512, 2, 1, 1><<<MT, 256>>>(nullptr, C0, b0);

    // layer 1
    k_sgemm<128, 1, 2, 0><<<MT, 256>>>(nullptr, W1, nullptr);
    k_aggregate<<<NN / 8, 256>>>();
    k_sgemm<512, 2, 1, 1><<<MT, 256>>>(nullptr, C1, b1);

    // classifier + log_softmax
    k_out<<<NN / 8, 256>>>(Wout, bout, out);
}

// round 5
// speedup vs baseline: 1.2306x; 1.2306x over previous
#include <cuda_runtime.h>
#include <math.h>
#include <stdint.h>

#define NN 40000
#define NE 640000
#define D 128
#define DC 512
#define NCLS 40
#define SCAN_NB ((NN + 255) / 256)   // 157
#define NT ((NN + 127) / 128)        // 313 tiles

// ---------------- device scratch ----------------
__device__ int   g_deg[NN];
__device__ float g_dinv[NN];
__device__ int   g_off[NN + 1];
__device__ int   g_pos[NN];
__device__ int   g_src[NE];
__device__ int   g_bsum[SCAN_NB];
__device__ __align__(16) float g_gbuf[NN * D];    // dinv-scaled hidden
__device__ __align__(16) float g_feat[NN * DC];   // [mean|add|min|max]
__device__ __align__(16) float g_x1[NN * D];      // layer output

// ---------------- tf32 helpers ----------------
__device__ __forceinline__ float tf32_hi(float x) {
    uint32_t u;
    asm("cvt.rna.tf32.f32 %0, %1;" : "=r"(u) : "f"(x));
    return __uint_as_float(u);
}
__device__ __forceinline__ void split4(float4 v, float4& h, float4& l) {
    h.x = tf32_hi(v.x); h.y = tf32_hi(v.y); h.z = tf32_hi(v.z); h.w = tf32_hi(v.w);
    l.x = v.x - h.x; l.y = v.y - h.y; l.z = v.z - h.z; l.w = v.w - h.w;
}
__device__ __forceinline__ void mma8(float* c, const uint32_t* a, const uint32_t* b) {
    asm volatile(
        "mma.sync.aligned.m16n8k8.row.col.f32.tf32.tf32.f32 "
        "{%0,%1,%2,%3}, {%4,%5,%6,%7}, {%8,%9}, {%0,%1,%2,%3};"
        : "+f"(c[0]), "+f"(c[1]), "+f"(c[2]), "+f"(c[3])
        : "r"(a[0]), "r"(a[1]), "r"(a[2]), "r"(a[3]), "r"(b[0]), "r"(b[1]));
}

// ---------------- small utilities ----------------
__device__ __forceinline__ int warp_iscan(int v) {
    #pragma unroll
    for (int d = 1; d < 32; d <<= 1) {
        int t = __shfl_up_sync(0xffffffffu, v, d);
        if ((threadIdx.x & 31) >= d) v += t;
    }
    return v;
}

// ---------------- graph preprocessing ----------------
__global__ void k_init() {
    int i = blockIdx.x * 256 + threadIdx.x;
    if (i < NN) g_deg[i] = 1;
}
__global__ void k_count(const int* __restrict__ ei) {
    int e = blockIdx.x * 256 + threadIdx.x;
    if (e < NE) atomicAdd(&g_deg[ei[NE + e]], 1);
}
__global__ void k_scan_a() {
    __shared__ int wsum[8];
    int i = blockIdx.x * 256 + threadIdx.x;
    int cnt = (i < NN) ? (g_deg[i] - 1) : 0;
    int inc = warp_iscan(cnt);
    int wid = threadIdx.x >> 5, lane = threadIdx.x & 31;
    if (lane == 31) wsum[wid] = inc;
    __syncthreads();
    if (wid == 0) {
        int v = (lane < 8) ? wsum[lane] : 0;
        v = warp_iscan(v);
        if (lane < 8) wsum[lane] = v;
    }
    __syncthreads();
    int base = wid ? wsum[wid - 1] : 0;
    if (i < NN) g_off[i] = base + inc - cnt;
    if (threadIdx.x == 255) g_bsum[blockIdx.x] = base + inc;
}
__global__ void k_scan_b() {
    __shared__ int wsum[8];
    int t = threadIdx.x;
    int v = (t < SCAN_NB) ? g_bsum[t] : 0;
    int inc = warp_iscan(v);
    int wid = t >> 5, lane = t & 31;
    if (lane == 31) wsum[wid] = inc;
    __syncthreads();
    if (wid == 0) {
        int u = (lane < 8) ? wsum[lane] : 0;
        u = warp_iscan(u);
        if (lane < 8) wsum[lane] = u;
    }
    __syncthreads();
    int base = wid ? wsum[wid - 1] : 0;
    if (t < SCAN_NB) g_bsum[t] = base + inc - v;
}
__global__ void k_scan_c() {
    int i = blockIdx.x * 256 + threadIdx.x;
    if (i < NN) {
        int o = g_off[i] + g_bsum[i >> 8];
        g_off[i] = o;
        g_pos[i] = o;
        g_dinv[i] = rsqrtf((float)g_deg[i]);
    }
    if (i == 0) g_off[NN] = NE;
}
__global__ void k_fill(const int* __restrict__ ei) {
    int e = blockIdx.x * 256 + threadIdx.x;
    if (e < NE) {
        int c = ei[NE + e];
        int p = atomicAdd(&g_pos[c], 1);
        g_src[p] = ei[e];
    }
}

// ---------------- aggregation: warp per node ----------------
__device__ __forceinline__ void upd(float4& s, float4& mn, float4& mx, float4 u) {
    s.x += u.x; s.y += u.y; s.z += u.z; s.w += u.w;
    mn.x = fminf(mn.x, u.x); mn.y = fminf(mn.y, u.y);
    mn.z = fminf(mn.z, u.z); mn.w = fminf(mn.w, u.w);
    mx.x = fmaxf(mx.x, u.x); mx.y = fmaxf(mx.y, u.y);
    mx.z = fmaxf(mx.z, u.z); mx.w = fmaxf(mx.w, u.w);
}
__global__ void __launch_bounds__(256) k_aggregate() {
    int w = threadIdx.x >> 5, lane = threadIdx.x & 31;
    int c = blockIdx.x * 8 + w;
    const float4* gv = (const float4*)g_gbuf;
    float4 v = gv[c * 32 + lane];
    float4 s = v, mn = v, mx = v;
    int e0 = g_off[c], e1 = g_off[c + 1];
    int j = e0;
    // unroll-4: front-batch indices then gathers for MLP
    for (; j + 4 <= e1; j += 4) {
        int r0 = __ldg(&g_src[j]);
        int r1 = __ldg(&g_src[j + 1]);
        int r2 = __ldg(&g_src[j + 2]);
        int r3 = __ldg(&g_src[j + 3]);
        float4 u0 = __ldg(&gv[r0 * 32 + lane]);
        float4 u1 = __ldg(&gv[r1 * 32 + lane]);
        float4 u2 = __ldg(&gv[r2 * 32 + lane]);
        float4 u3 = __ldg(&gv[r3 * 32 + lane]);
        upd(s, mn, mx, u0);
        upd(s, mn, mx, u1);
        upd(s, mn, mx, u2);
        upd(s, mn, mx, u3);
    }
    for (; j < e1; j++) {
        int r = __ldg(&g_src[j]);
        upd(s, mn, mx, __ldg(&gv[r * 32 + lane]));
    }
    float di  = g_dinv[c];
    float rdg = 1.0f / (float)g_deg[c];
    float4* fv = (float4*)g_feat;
    int b = c * (DC / 4);
    float4 ad = make_float4(di * s.x, di * s.y, di * s.z, di * s.w);
    fv[b + lane]      = make_float4(ad.x * rdg, ad.y * rdg, ad.z * rdg, ad.w * rdg);
    fv[b + 32 + lane] = ad;
    fv[b + 64 + lane] = make_float4(di * mn.x, di * mn.y, di * mn.z, di * mn.w);
    fv[b + 96 + lane] = make_float4(di * mx.x, di * mx.y, di * mx.z, di * mx.w);
}

// ---------------- tf32 mma.sync 3-pass GEMM ----------------
// C[M,128] = A[M,K] @ B[128,K]^T; 128x128 CTA tile; 8 warps as 4x2 (32x64 each).
// 3 passes accumulate a_hi*b_hi + a_lo*b_hi + a_hi*b_lo into the same fp32 acc.
// ASRC: 0 = Aext, 1 = g_feat, 2 = g_x1 ; CDST: 0 = g_gbuf, 1 = g_x1
// EPI 1: C = g_dinv[m]*acc ; EPI 2: C = relu(acc + bias[n])
#define SSTR 20   // smem row stride (conflict-free for frag loads)

template <int K, int EPI, int ASRC, int CDST>
__global__ void __launch_bounds__(256, 2) k_mma(const float* __restrict__ Aext,
                                                const float* __restrict__ B,
                                                const float* __restrict__ bias_p) {
    const float* A = (ASRC == 0) ? Aext : (ASRC == 1 ? (const float*)g_feat
                                                     : (const float*)g_x1);
    float* C = (CDST == 0) ? g_gbuf : g_x1;

    __shared__ float Ah[128 * SSTR], Al[128 * SSTR], Bh[128 * SSTR], Bl[128 * SSTR];

    const int tid = threadIdx.x;
    const int wid = tid >> 5, lane = tid & 31;
    const int g = lane >> 2, tig = lane & 3;
    const int wr = wid >> 1, wc = wid & 1;   // warp row (0..3), warp col (0..1)
    const int m0 = blockIdx.x * 128;

    float acc[2][8][4];
    #pragma unroll
    for (int mt = 0; mt < 2; mt++)
        #pragma unroll
        for (int nt = 0; nt < 8; nt++)
            #pragma unroll
            for (int q = 0; q < 4; q++) acc[mt][nt][q] = 0.f;

    for (int ch = 0; ch < K / 16; ch++) {
        // load + split chunk: A[128x16], B[128x16]
        #pragma unroll
        for (int j = 0; j < 2; j++) {
            const int idx = tid + j * 256;          // 0..511
            const int row = idx >> 2, c4 = idx & 3;
            float4 av = make_float4(0.f, 0.f, 0.f, 0.f);
            if (m0 + row < NN)
                av = *(const float4*)(A + (size_t)(m0 + row) * K + ch * 16 + c4 * 4);
            const float4 bv = *(const float4*)(B + (size_t)row * K + ch * 16 + c4 * 4);
            float4 h, l;
            split4(av, h, l);
            float* pa = &Ah[row * SSTR + c4 * 4];
            float* qa = &Al[row * SSTR + c4 * 4];
            pa[0] = h.x; pa[1] = h.y; pa[2] = h.z; pa[3] = h.w;
            qa[0] = l.x; qa[1] = l.y; qa[2] = l.z; qa[3] = l.w;
            split4(bv, h, l);
            float* pb = &Bh[row * SSTR + c4 * 4];
            float* qb = &Bl[row * SSTR + c4 * 4];
            pb[0] = h.x; pb[1] = h.y; pb[2] = h.z; pb[3] = h.w;
            qb[0] = l.x; qb[1] = l.y; qb[2] = l.z; qb[3] = l.w;
        }
        __syncthreads();

        #pragma unroll
        for (int ks = 0; ks < 2; ks++) {
            const int kb = ks * 8;
            uint32_t bb[8][2], aa[2][4], a2[2][4];
            // B_hi fragments
            #pragma unroll
            for (int nt = 0; nt < 8; nt++) {
                const int n = wc * 64 + nt * 8 + g;
                bb[nt][0] = __float_as_uint(Bh[n * SSTR + kb + tig]);
                bb[nt][1] = __float_as_uint(Bh[n * SSTR + kb + tig + 4]);
            }
            // A_hi fragments
            #pragma unroll
            for (int mt = 0; mt < 2; mt++) {
                const int m = wr * 32 + mt * 16 + g;
                aa[mt][0] = __float_as_uint(Ah[m * SSTR + kb + tig]);
                aa[mt][1] = __float_as_uint(Ah[(m + 8) * SSTR + kb + tig]);
                aa[mt][2] = __float_as_uint(Ah[m * SSTR + kb + tig + 4]);
                aa[mt][3] = __float_as_uint(Ah[(m + 8) * SSTR + kb + tig + 4]);
            }
            // pass 1: ah*bh
            #pragma unroll
            for (int mt = 0; mt < 2; mt++)
                #pragma unroll
                for (int nt = 0; nt < 8; nt++) mma8(acc[mt][nt], aa[mt], bb[nt]);
            // A_lo fragments; pass 2: al*bh
            #pragma unroll
            for (int mt = 0; mt < 2; mt++) {
                const int m = wr * 32 + mt * 16 + g;
                a2[mt][0] = __float_as_uint(Al[m * SSTR + kb + tig]);
                a2[mt][1] = __float_as_uint(Al[(m + 8) * SSTR + kb + tig]);
                a2[mt][2] = __float_as_uint(Al[m * SSTR + kb + tig + 4]);
                a2[mt][3] = __float_as_uint(Al[(m + 8) * SSTR + kb + tig + 4]);
            }
            #pragma unroll
            for (int mt = 0; mt < 2; mt++)
                #pragma unroll
                for (int nt = 0; nt < 8; nt++) mma8(acc[mt][nt], a2[mt], bb[nt]);
            // B_lo fragments; pass 3: ah*bl
            #pragma unroll
            for (int nt = 0; nt < 8; nt++) {
                const int n = wc * 64 + nt * 8 + g;
                bb[nt][0] = __float_as_uint(Bl[n * SSTR + kb + tig]);
                bb[nt][1] = __float_as_uint(Bl[n * SSTR + kb + tig + 4]);
            }
            #pragma unroll
            for (int mt = 0; mt < 2; mt++)
                #pragma unroll
                for (int nt = 0; nt < 8; nt++) mma8(acc[mt][nt], aa[mt], bb[nt]);
        }
        __syncthreads();
    }

    // epilogue
    #pragma unroll
    for (int mt = 0; mt < 2; mt++) {
        const int r0 = m0 + wr * 32 + mt * 16 + g;
        const int r1 = r0 + 8;
        if (EPI == 1) {
            const float d0 = (r0 < NN) ? g_dinv[r0] : 0.f;
            const float d1 = (r1 < NN) ? g_dinv[r1] : 0.f;
            #pragma unroll
            for (int nt = 0; nt < 8; nt++) {
                const int col = wc * 64 + nt * 8 + tig * 2;
                if (r0 < NN)
                    *(float2*)&C[(size_t)r0 * 128 + col] =
                        make_float2(d0 * acc[mt][nt][0], d0 * acc[mt][nt][1]);
                if (r1 < NN)
                    *(float2*)&C[(size_t)r1 * 128 + col] =
                        make_float2(d1 * acc[mt][nt][2], d1 * acc[mt][nt][3]);
            }
        } else {
            #pragma unroll
            for (int nt = 0; nt < 8; nt++) {
                const int col = wc * 64 + nt * 8 + tig * 2;
                const float2 bv = *(const float2*)&bias_p[col];
                if (r0 < NN)
                    *(float2*)&C[(size_t)r0 * 128 + col] =
                        make_float2(fmaxf(acc[mt][nt][0] + bv.x, 0.f),
                                    fmaxf(acc[mt][nt][1] + bv.y, 0.f));
                if (r1 < NN)
                    *(float2*)&C[(size_t)r1 * 128 + col] =
                        make_float2(fmaxf(acc[mt][nt][2] + bv.x, 0.f),
                                    fmaxf(acc[mt][nt][3] + bv.y, 0.f));
            }
        }
    }
}

// ---------------- classifier + log_softmax: warp per node ----------------
__global__ void __launch_bounds__(256) k_out(const float* __restrict__ W,
                                             const float* __restrict__ bias,
                                             float* __restrict__ out) {
    __shared__ float ws[NCLS * 129];
    __shared__ float xs[8][128];
    __shared__ float bs[NCLS];
    int tid = threadIdx.x;
    for (int i = tid; i < NCLS * D; i += 256) {
        int c = i >> 7, k = i & 127;
        ws[c * 129 + k] = W[i];
    }
    if (tid < NCLS) bs[tid] = bias[tid];
    int w = tid >> 5, lane = tid & 31;
    int node = blockIdx.x * 8 + w;
    #pragma unroll
    for (int q = 0; q < 4; q++)
        xs[w][lane + 32 * q] = g_x1[node * D + lane + 32 * q];
    __syncthreads();

    int c2 = 32 + (lane & 7);
    float acc0 = bs[lane];
    float acc1 = bs[c2];
    #pragma unroll 8
    for (int k = 0; k < D; k++) {
        float xv = xs[w][k];
        acc0 = fmaf(xv, ws[lane * 129 + k], acc0);
        acc1 = fmaf(xv, ws[c2 * 129 + k], acc1);
    }
    bool v1 = (lane < 8);
    float m = fmaxf(acc0, v1 ? acc1 : -1e30f);
    #pragma unroll
    for (int d = 16; d; d >>= 1) m = fmaxf(m, __shfl_xor_sync(0xffffffffu, m, d));
    float s = expf(acc0 - m) + (v1 ? expf(acc1 - m) : 0.f);
    #pragma unroll
    for (int d = 16; d; d >>= 1) s += __shfl_xor_sync(0xffffffffu, s, d);
    float lse = m + logf(s);
    out[node * NCLS + lane] = acc0 - lse;
    if (v1) out[node * NCLS + 32 + lane] = acc1 - lse;
}

// ---------------- launch ----------------
extern "C" void kernel_launch(void* const* d_in, const int* in_sizes, int n_in,
                              void* d_out, int out_size) {
    (void)in_sizes; (void)n_in; (void)out_size;
    const float* x    = (const float*)d_in[0];
    const int*   ei   = (const int*)d_in[1];
    const float* W0   = (const float*)d_in[2];
    const float* C0   = (const float*)d_in[3];
    const float* b0   = (const float*)d_in[4];
    const float* W1   = (const float*)d_in[5];
    const float* C1   = (const float*)d_in[6];
    const float* b1   = (const float*)d_in[7];
    const float* Wout = (const float*)d_in[8];
    const float* bout = (const float*)d_in[9];
    float* out = (float*)d_out;

    const int EB = (NE + 255) / 256;

    k_init  <<<SCAN_NB, 256>>>();
    k_count <<<EB, 256>>>(ei);
    k_scan_a<<<SCAN_NB, 256>>>();
    k_scan_b<<<1, 256>>>();
    k_scan_c<<<SCAN_NB, 256>>>();
    k_fill  <<<EB, 256>>>(ei);

    // layer 0
    k_mma<128, 1, 0, 0><<<NT, 256>>>(x, W0, nullptr);
    k_aggregate<<<NN / 8, 256>>>();
    k_mma<512, 2, 1, 1><<<NT, 256>>>(nullptr, C0, b0);

    // layer 1
    k_mma<128, 1, 2, 0><<<NT, 256>>>(nullptr, W1, nullptr);
    k_aggregate<<<NN / 8, 256>>>();
    k_mma<512, 2, 1, 1><<<NT, 256>>>(nullptr, C1, b1);

    k_out<<<NN / 8, 256>>>(Wout, bout, out);
}

// round 7
// speedup vs baseline: 1.2789x; 1.0392x over previous
#include <cuda_runtime.h>
#include <math.h>
#include <stdint.h>

#define NN 40000
#define NE 640000
#define D 128
#define DC 512
#define NCLS 40
#define SCAN_NB ((NN + 255) / 256)   // 157
#define NT ((NN + 127) / 128)        // 313 tiles

// ---------------- device scratch ----------------
__device__ int   g_deg[NN];
__device__ float g_dinv[NN];
__device__ int   g_off[NN + 1];
__device__ int   g_pos[NN];
__device__ int   g_src[NE];
__device__ int   g_bsum[SCAN_NB];
__device__ __align__(16) float g_gbuf[NN * D];    // hidden h (unscaled)
__device__ __align__(16) float g_feat[NN * DC];   // [mean|add|min|max]
__device__ __align__(16) float g_x1[NN * D];      // layer output

// ---------------- tf32 helpers ----------------
__device__ __forceinline__ float tf32_hi(float x) {
    uint32_t u;
    asm("cvt.rna.tf32.f32 %0, %1;" : "=r"(u) : "f"(x));
    return __uint_as_float(u);
}
__device__ __forceinline__ void split4(float4 v, float4& h, float4& l) {
    h.x = tf32_hi(v.x); h.y = tf32_hi(v.y); h.z = tf32_hi(v.z); h.w = tf32_hi(v.w);
    l.x = v.x - h.x; l.y = v.y - h.y; l.z = v.z - h.z; l.w = v.w - h.w;
}
__device__ __forceinline__ void mma8(float* c, const uint32_t* a, const uint32_t* b) {
    asm volatile(
        "mma.sync.aligned.m16n8k8.row.col.f32.tf32.tf32.f32 "
        "{%0,%1,%2,%3}, {%4,%5,%6,%7}, {%8,%9}, {%0,%1,%2,%3};"
        : "+f"(c[0]), "+f"(c[1]), "+f"(c[2]), "+f"(c[3])
        : "r"(a[0]), "r"(a[1]), "r"(a[2]), "r"(a[3]), "r"(b[0]), "r"(b[1]));
}

// ---------------- small utilities ----------------
__device__ __forceinline__ int warp_iscan(int v) {
    #pragma unroll
    for (int d = 1; d < 32; d <<= 1) {
        int t = __shfl_up_sync(0xffffffffu, v, d);
        if ((threadIdx.x & 31) >= d) v += t;
    }
    return v;
}

// ---------------- graph preprocessing ----------------
__global__ void k_init() {
    int i = blockIdx.x * 256 + threadIdx.x;
    if (i < NN) g_deg[i] = 1;
}
__global__ void k_count(const int* __restrict__ ei) {
    int e = blockIdx.x * 256 + threadIdx.x;
    if (e < NE) atomicAdd(&g_deg[ei[NE + e]], 1);
}
__global__ void k_scan_a() {
    __shared__ int wsum[8];
    int i = blockIdx.x * 256 + threadIdx.x;
    int cnt = (i < NN) ? (g_deg[i] - 1) : 0;
    int inc = warp_iscan(cnt);
    int wid = threadIdx.x >> 5, lane = threadIdx.x & 31;
    if (lane == 31) wsum[wid] = inc;
    __syncthreads();
    if (wid == 0) {
        int v = (lane < 8) ? wsum[lane] : 0;
        v = warp_iscan(v);
        if (lane < 8) wsum[lane] = v;
    }
    __syncthreads();
    int base = wid ? wsum[wid - 1] : 0;
    if (i < NN) g_off[i] = base + inc - cnt;
    if (threadIdx.x == 255) g_bsum[blockIdx.x] = base + inc;
}
__global__ void k_scan_b() {
    __shared__ int wsum[8];
    int t = threadIdx.x;
    int v = (t < SCAN_NB) ? g_bsum[t] : 0;
    int inc = warp_iscan(v);
    int wid = t >> 5, lane = t & 31;
    if (lane == 31) wsum[wid] = inc;
    __syncthreads();
    if (wid == 0) {
        int u = (lane < 8) ? wsum[lane] : 0;
        u = warp_iscan(u);
        if (lane < 8) wsum[lane] = u;
    }
    __syncthreads();
    int base = wid ? wsum[wid - 1] : 0;
    if (t < SCAN_NB) g_bsum[t] = base + inc - v;
}
__global__ void k_scan_c() {
    int i = blockIdx.x * 256 + threadIdx.x;
    if (i < NN) {
        int o = g_off[i] + g_bsum[i >> 8];
        g_off[i] = o;
        g_pos[i] = o;
        g_dinv[i] = rsqrtf((float)g_deg[i]);
    }
    if (i == 0) g_off[NN] = NE;
}
__global__ void k_fill(const int* __restrict__ ei) {
    int e = blockIdx.x * 256 + threadIdx.x;
    if (e < NE) {
        int c = ei[NE + e];
        int p = atomicAdd(&g_pos[c], 1);
        g_src[p] = ei[e];
    }
}

// ---------------- aggregation: warp per node, dinv applied at gather ----------------
__device__ __forceinline__ void upd(float4& s, float4& mn, float4& mx, float d, float4 u) {
    u.x *= d; u.y *= d; u.z *= d; u.w *= d;
    s.x += u.x; s.y += u.y; s.z += u.z; s.w += u.w;
    mn.x = fminf(mn.x, u.x); mn.y = fminf(mn.y, u.y);
    mn.z = fminf(mn.z, u.z); mn.w = fminf(mn.w, u.w);
    mx.x = fmaxf(mx.x, u.x); mx.y = fmaxf(mx.y, u.y);
    mx.z = fmaxf(mx.z, u.z); mx.w = fmaxf(mx.w, u.w);
}
__global__ void __launch_bounds__(256) k_aggregate() {
    int w = threadIdx.x >> 5, lane = threadIdx.x & 31;
    int c = blockIdx.x * 8 + w;
    const float4* gv = (const float4*)g_gbuf;
    float dc = g_dinv[c];
    float4 hc = gv[c * 32 + lane];
    float4 v = make_float4(dc * hc.x, dc * hc.y, dc * hc.z, dc * hc.w);
    float4 s = v, mn = v, mx = v;
    int e0 = g_off[c], e1 = g_off[c + 1];
    int j = e0;
    for (; j + 4 <= e1; j += 4) {
        int r0 = __ldg(&g_src[j]);
        int r1 = __ldg(&g_src[j + 1]);
        int r2 = __ldg(&g_src[j + 2]);
        int r3 = __ldg(&g_src[j + 3]);
        float d0 = __ldg(&g_dinv[r0]);
        float d1 = __ldg(&g_dinv[r1]);
        float d2 = __ldg(&g_dinv[r2]);
        float d3 = __ldg(&g_dinv[r3]);
        float4 u0 = __ldg(&gv[r0 * 32 + lane]);
        float4 u1 = __ldg(&gv[r1 * 32 + lane]);
        float4 u2 = __ldg(&gv[r2 * 32 + lane]);
        float4 u3 = __ldg(&gv[r3 * 32 + lane]);
        upd(s, mn, mx, d0, u0);
        upd(s, mn, mx, d1, u1);
        upd(s, mn, mx, d2, u2);
        upd(s, mn, mx, d3, u3);
    }
    for (; j < e1; j++) {
        int r = __ldg(&g_src[j]);
        float d = __ldg(&g_dinv[r]);
        upd(s, mn, mx, d, __ldg(&gv[r * 32 + lane]));
    }
    float rdg = 1.0f / (float)g_deg[c];
    float4* fv = (float4*)g_feat;
    int b = c * (DC / 4);
    float4 ad = make_float4(dc * s.x, dc * s.y, dc * s.z, dc * s.w);
    fv[b + lane]      = make_float4(ad.x * rdg, ad.y * rdg, ad.z * rdg, ad.w * rdg);
    fv[b + 32 + lane] = ad;
    fv[b + 64 + lane] = make_float4(dc * mn.x, dc * mn.y, dc * mn.z, dc * mn.w);
    fv[b + 96 + lane] = make_float4(dc * mx.x, dc * mx.y, dc * mx.z, dc * mx.w);
}

// ---------------- tf32 mma.sync 3-pass GEMM, register double-buffered ----------------
// C[M,128] = A[M,K] @ B[128,K]^T; 128x128 CTA tile; 8 warps as 4x2 (32x64 each).
// EPI 0: C = acc ; EPI 2: C = relu(acc + bias[n])
#define SSTR 20   // smem row stride (conflict-free for frag loads)

template <int K, int EPI, int ASRC, int CDST>
__global__ void __launch_bounds__(256, 2) k_mma(const float* __restrict__ Aext,
                                                const float* __restrict__ B,
                                                const float* __restrict__ bias_p) {
    const float* A = (ASRC == 0) ? Aext : (ASRC == 1 ? (const float*)g_feat
                                                     : (const float*)g_x1);
    float* C = (CDST == 0) ? g_gbuf : g_x1;

    __shared__ float Ah[128 * SSTR], Al[128 * SSTR], Bh[128 * SSTR], Bl[128 * SSTR];

    const int tid = threadIdx.x;
    const int wid = tid >> 5, lane = tid & 31;
    const int g = lane >> 2, tig = lane & 3;
    const int wr = wid >> 1, wc = wid & 1;
    const int m0 = blockIdx.x * 128;
    constexpr int NC = K / 16;

    // per-thread load geometry (two 4-row-groups of the 128x16 chunk)
    int rowj[2], c4j[2];
    bool okA[2];
    #pragma unroll
    for (int j = 0; j < 2; j++) {
        const int idx = tid + j * 256;
        rowj[j] = idx >> 2;
        c4j[j]  = idx & 3;
        okA[j]  = (m0 + rowj[j]) < NN;
    }

    float acc[2][8][4];
    #pragma unroll
    for (int mt = 0; mt < 2; mt++)
        #pragma unroll
        for (int nt = 0; nt < 8; nt++)
            #pragma unroll
            for (int q = 0; q < 4; q++) acc[mt][nt][q] = 0.f;

    float4 avB[2], bvB[2];
    // prologue: load chunk 0
    #pragma unroll
    for (int j = 0; j < 2; j++) {
        avB[j] = make_float4(0.f, 0.f, 0.f, 0.f);
        if (okA[j])
            avB[j] = *(const float4*)(A + (size_t)(m0 + rowj[j]) * K + c4j[j] * 4);
        bvB[j] = *(const float4*)(B + (size_t)rowj[j] * K + c4j[j] * 4);
    }

    #pragma unroll 1
    for (int ch = 0; ch < NC; ch++) {
        // split + store current buffered chunk
        #pragma unroll
        for (int j = 0; j < 2; j++) {
            float4 h, l;
            split4(avB[j], h, l);
            float* pa = &Ah[rowj[j] * SSTR + c4j[j] * 4];
            float* qa = &Al[rowj[j] * SSTR + c4j[j] * 4];
            pa[0] = h.x; pa[1] = h.y; pa[2] = h.z; pa[3] = h.w;
            qa[0] = l.x; qa[1] = l.y; qa[2] = l.z; qa[3] = l.w;
            split4(bvB[j], h, l);
            float* pb = &Bh[rowj[j] * SSTR + c4j[j] * 4];
            float* qb = &Bl[rowj[j] * SSTR + c4j[j] * 4];
            pb[0] = h.x; pb[1] = h.y; pb[2] = h.z; pb[3] = h.w;
            qb[0] = l.x; qb[1] = l.y; qb[2] = l.z; qb[3] = l.w;
        }
        __syncthreads();

        // issue next chunk's loads (latency hides under MMA phase)
        if (ch + 1 < NC) {
            const int kof = (ch + 1) * 16;
            #pragma unroll
            for (int j = 0; j < 2; j++) {
                avB[j] = make_float4(0.f, 0.f, 0.f, 0.f);
                if (okA[j])
                    avB[j] = *(const float4*)(A + (size_t)(m0 + rowj[j]) * K + kof + c4j[j] * 4);
                bvB[j] = *(const float4*)(B + (size_t)rowj[j] * K + kof + c4j[j] * 4);
            }
        }

        #pragma unroll
        for (int ks = 0; ks < 2; ks++) {
            const int kb = ks * 8;
            uint32_t bb[8][2], aa[2][4], a2[2][4];
            #pragma unroll
            for (int nt = 0; nt < 8; nt++) {
                const int n = wc * 64 + nt * 8 + g;
                bb[nt][0] = __float_as_uint(Bh[n * SSTR + kb + tig]);
                bb[nt][1] = __float_as_uint(Bh[n * SSTR + kb + tig + 4]);
            }
            #pragma unroll
            for (int mt = 0; mt < 2; mt++) {
                const int m = wr * 32 + mt * 16 + g;
                aa[mt][0] = __float_as_uint(Ah[m * SSTR + kb + tig]);
                aa[mt][1] = __float_as_uint(Ah[(m + 8) * SSTR + kb + tig]);
                aa[mt][2] = __float_as_uint(Ah[m * SSTR + kb + tig + 4]);
                aa[mt][3] = __float_as_uint(Ah[(m + 8) * SSTR + kb + tig + 4]);
            }
            // pass 1: ah*bh
            #pragma unroll
            for (int mt = 0; mt < 2; mt++)
                #pragma unroll
                for (int nt = 0; nt < 8; nt++) mma8(acc[mt][nt], aa[mt], bb[nt]);
            // pass 2: al*bh
            #pragma unroll
            for (int mt = 0; mt < 2; mt++) {
                const int m = wr * 32 + mt * 16 + g;
                a2[mt][0] = __float_as_uint(Al[m * SSTR + kb + tig]);
                a2[mt][1] = __float_as_uint(Al[(m + 8) * SSTR + kb + tig]);
                a2[mt][2] = __float_as_uint(Al[m * SSTR + kb + tig + 4]);
                a2[mt][3] = __float_as_uint(Al[(m + 8) * SSTR + kb + tig + 4]);
            }
            #pragma unroll
            for (int mt = 0; mt < 2; mt++)
                #pragma unroll
                for (int nt = 0; nt < 8; nt++) mma8(acc[mt][nt], a2[mt], bb[nt]);
            // pass 3: ah*bl
            #pragma unroll
            for (int nt = 0; nt < 8; nt++) {
                const int n = wc * 64 + nt * 8 + g;
                bb[nt][0] = __float_as_uint(Bl[n * SSTR + kb + tig]);
                bb[nt][1] = __float_as_uint(Bl[n * SSTR + kb + tig + 4]);
            }
            #pragma unroll
            for (int mt = 0; mt < 2; mt++)
                #pragma unroll
                for (int nt = 0; nt < 8; nt++) mma8(acc[mt][nt], aa[mt], bb[nt]);
        }
        __syncthreads();
    }

    // epilogue
    #pragma unroll
    for (int mt = 0; mt < 2; mt++) {
        const int r0 = m0 + wr * 32 + mt * 16 + g;
        const int r1 = r0 + 8;
        if (EPI == 0) {
            #pragma unroll
            for (int nt = 0; nt < 8; nt++) {
                const int col = wc * 64 + nt * 8 + tig * 2;
                if (r0 < NN)
                    *(float2*)&C[(size_t)r0 * 128 + col] =
                        make_float2(acc[mt][nt][0], acc[mt][nt][1]);
                if (r1 < NN)
                    *(float2*)&C[(size_t)r1 * 128 + col] =
                        make_float2(acc[mt][nt][2], acc[mt][nt][3]);
            }
        } else {
            #pragma unroll
            for (int nt = 0; nt < 8; nt++) {
                const int col = wc * 64 + nt * 8 + tig * 2;
                const float2 bv = *(const float2*)&bias_p[col];
                if (r0 < NN)
                    *(float2*)&C[(size_t)r0 * 128 + col] =
                        make_float2(fmaxf(acc[mt][nt][0] + bv.x, 0.f),
                                    fmaxf(acc[mt][nt][1] + bv.y, 0.f));
                if (r1 < NN)
                    *(float2*)&C[(size_t)r1 * 128 + col] =
                        make_float2(fmaxf(acc[mt][nt][2] + bv.x, 0.f),
                                    fmaxf(acc[mt][nt][3] + bv.y, 0.f));
            }
        }
    }
}

// ---------------- classifier + log_softmax: warp per node ----------------
__global__ void __launch_bounds__(256) k_out(const float* __restrict__ W,
                                             const float* __restrict__ bias,
                                             float* __restrict__ out) {
    __shared__ float ws[NCLS * 129];
    __shared__ float xs[8][128];
    __shared__ float bs[NCLS];
    int tid = threadIdx.x;
    for (int i = tid; i < NCLS * D; i += 256) {
        int c = i >> 7, k = i & 127;
        ws[c * 129 + k] = W[i];
    }
    if (tid < NCLS) bs[tid] = bias[tid];
    int w = tid >> 5, lane = tid & 31;
    int node = blockIdx.x * 8 + w;
    #pragma unroll
    for (int q = 0; q < 4; q++)
        xs[w][lane + 32 * q] = g_x1[node * D + lane + 32 * q];
    __syncthreads();

    int c2 = 32 + (lane & 7);
    float acc0 = bs[lane];
    float acc1 = bs[c2];
    #pragma unroll 8
    for (int k = 0; k < D; k++) {
        float xv = xs[w][k];
        acc0 = fmaf(xv, ws[lane * 129 + k], acc0);
        acc1 = fmaf(xv, ws[c2 * 129 + k], acc1);
    }
    bool v1 = (lane < 8);
    float m = fmaxf(acc0, v1 ? acc1 : -1e30f);
    #pragma unroll
    for (int d = 16; d; d >>= 1) m = fmaxf(m, __shfl_xor_sync(0xffffffffu, m, d));
    float s = expf(acc0 - m) + (v1 ? expf(acc1 - m) : 0.f);
    #pragma unroll
    for (int d = 16; d; d >>= 1) s += __shfl_xor_sync(0xffffffffu, s, d);
    float lse = m + logf(s);
    out[node * NCLS + lane] = acc0 - lse;
    if (v1) out[node * NCLS + 32 + lane] = acc1 - lse;
}

// ---------------- launch ----------------
extern "C" void kernel_launch(void* const* d_in, const int* in_sizes, int n_in,
                              void* d_out, int out_size) {
    (void)in_sizes; (void)n_in; (void)out_size;
    const float* x    = (const float*)d_in[0];
    const int*   ei   = (const int*)d_in[1];
    const float* W0   = (const float*)d_in[2];
    const float* C0   = (const float*)d_in[3];
    const float* b0   = (const float*)d_in[4];
    const float* W1   = (const float*)d_in[5];
    const float* C1   = (const float*)d_in[6];
    const float* b1   = (const float*)d_in[7];
    const float* Wout = (const float*)d_in[8];
    const float* bout = (const float*)d_in[9];
    float* out = (float*)d_out;

    const int EB = (NE + 255) / 256;

    // build (first 3) then lin-GEMM L0 as launch #4 (graph-independent) so
    // ncu's fixed capture window lands on a GEMM kernel.
    k_init  <<<SCAN_NB, 256>>>();
    k_count <<<EB, 256>>>(ei);
    k_scan_a<<<SCAN_NB, 256>>>();
    k_mma<128, 0, 0, 0><<<NT, 256>>>(x, W0, nullptr);      // h0 = x @ W0^T  [PROFILED]
    k_scan_b<<<1, 256>>>();
    k_scan_c<<<SCAN_NB, 256>>>();
    k_fill  <<<EB, 256>>>(ei);

    // layer 0 aggregate + combine
    k_aggregate<<<NN / 8, 256>>>();
    k_mma<512, 2, 1, 1><<<NT, 256>>>(nullptr, C0, b0);

    // layer 1
    k_mma<128, 0, 2, 0><<<NT, 256>>>(nullptr, W1, nullptr);
    k_aggregate<<<NN / 8, 256>>>();
    k_mma<512, 2, 1, 1><<<NT, 256>>>(nullptr, C1, b1);

    k_out<<<NN / 8, 256>>>(Wout, bout, out);
}

// round 8
// speedup vs baseline: 1.7749x; 1.3878x over previous
#include <cuda_runtime.h>
#include <math.h>
#include <stdint.h>

#define NN 40000
#define NE 640000
#define D 128
#define DC 512
#define NCLS 40
#define SCAN_NB ((NN + 255) / 256)   // 157
#define NT ((NN + 127) / 128)        // 313 tiles

// ---------------- device scratch ----------------
__device__ int   g_deg[NN];
__device__ float g_dinv[NN];
__device__ int   g_off[NN + 1];
__device__ int   g_pos[NN];
__device__ int   g_src[NE];
__device__ int   g_bsum[SCAN_NB];
__device__ __align__(16) float g_gbuf[NN * D];    // hidden h (unscaled)
__device__ __align__(16) float g_feat[NN * DC];   // [mean|add|min|max]
__device__ __align__(16) float g_x1[NN * D];      // layer output

// ---------------- bf16 split helpers ----------------
// x = hi + lo with hi = bf16(x), lo = bf16(x - hi): ~16 effective mantissa bits.
__device__ __forceinline__ void split2(float x0, float x1, uint32_t& hi2, uint32_t& lo2) {
    asm("cvt.rn.bf16x2.f32 %0, %1, %2;" : "=r"(hi2) : "f"(x1), "f"(x0));
    float h0 = __uint_as_float(hi2 << 16);
    float h1 = __uint_as_float(hi2 & 0xffff0000u);
    float l0 = x0 - h0, l1 = x1 - h1;
    asm("cvt.rn.bf16x2.f32 %0, %1, %2;" : "=r"(lo2) : "f"(l1), "f"(l0));
}
__device__ __forceinline__ void mma16(float* c, const uint32_t* a, const uint32_t* b) {
    asm volatile(
        "mma.sync.aligned.m16n8k16.row.col.f32.bf16.bf16.f32 "
        "{%0,%1,%2,%3}, {%4,%5,%6,%7}, {%8,%9}, {%0,%1,%2,%3};"
        : "+f"(c[0]), "+f"(c[1]), "+f"(c[2]), "+f"(c[3])
        : "r"(a[0]), "r"(a[1]), "r"(a[2]), "r"(a[3]), "r"(b[0]), "r"(b[1]));
}

// ---------------- small utilities ----------------
__device__ __forceinline__ int warp_iscan(int v) {
    #pragma unroll
    for (int d = 1; d < 32; d <<= 1) {
        int t = __shfl_up_sync(0xffffffffu, v, d);
        if ((threadIdx.x & 31) >= d) v += t;
    }
    return v;
}

// ---------------- graph preprocessing ----------------
__global__ void k_init() {
    int i = blockIdx.x * 256 + threadIdx.x;
    if (i < NN) g_deg[i] = 1;
}
__global__ void k_count(const int* __restrict__ ei) {
    int e = blockIdx.x * 256 + threadIdx.x;
    if (e < NE) atomicAdd(&g_deg[ei[NE + e]], 1);
}
__global__ void k_scan_a() {
    __shared__ int wsum[8];
    int i = blockIdx.x * 256 + threadIdx.x;
    int cnt = (i < NN) ? (g_deg[i] - 1) : 0;
    int inc = warp_iscan(cnt);
    int wid = threadIdx.x >> 5, lane = threadIdx.x & 31;
    if (lane == 31) wsum[wid] = inc;
    __syncthreads();
    if (wid == 0) {
        int v = (lane < 8) ? wsum[lane] : 0;
        v = warp_iscan(v);
        if (lane < 8) wsum[lane] = v;
    }
    __syncthreads();
    int base = wid ? wsum[wid - 1] : 0;
    if (i < NN) g_off[i] = base + inc - cnt;
    if (threadIdx.x == 255) g_bsum[blockIdx.x] = base + inc;
}
__global__ void k_scan_b() {
    __shared__ int wsum[8];
    int t = threadIdx.x;
    int v = (t < SCAN_NB) ? g_bsum[t] : 0;
    int inc = warp_iscan(v);
    int wid = t >> 5, lane = t & 31;
    if (lane == 31) wsum[wid] = inc;
    __syncthreads();
    if (wid == 0) {
        int u = (lane < 8) ? wsum[lane] : 0;
        u = warp_iscan(u);
        if (lane < 8) wsum[lane] = u;
    }
    __syncthreads();
    int base = wid ? wsum[wid - 1] : 0;
    if (t < SCAN_NB) g_bsum[t] = base + inc - v;
}
__global__ void k_scan_c() {
    int i = blockIdx.x * 256 + threadIdx.x;
    if (i < NN) {
        int o = g_off[i] + g_bsum[i >> 8];
        g_off[i] = o;
        g_pos[i] = o;
        g_dinv[i] = rsqrtf((float)g_deg[i]);
    }
    if (i == 0) g_off[NN] = NE;
}
__global__ void k_fill(const int* __restrict__ ei) {
    int e = blockIdx.x * 256 + threadIdx.x;
    if (e < NE) {
        int c = ei[NE + e];
        int p = atomicAdd(&g_pos[c], 1);
        g_src[p] = ei[e];
    }
}

// ---------------- aggregation: warp per node, dinv applied at gather ----------------
__device__ __forceinline__ void upd(float4& s, float4& mn, float4& mx, float d, float4 u) {
    u.x *= d; u.y *= d; u.z *= d; u.w *= d;
    s.x += u.x; s.y += u.y; s.z += u.z; s.w += u.w;
    mn.x = fminf(mn.x, u.x); mn.y = fminf(mn.y, u.y);
    mn.z = fminf(mn.z, u.z); mn.w = fminf(mn.w, u.w);
    mx.x = fmaxf(mx.x, u.x); mx.y = fmaxf(mx.y, u.y);
    mx.z = fmaxf(mx.z, u.z); mx.w = fmaxf(mx.w, u.w);
}
__global__ void __launch_bounds__(256) k_aggregate() {
    int w = threadIdx.x >> 5, lane = threadIdx.x & 31;
    int c = blockIdx.x * 8 + w;
    const float4* gv = (const float4*)g_gbuf;
    float dc = g_dinv[c];
    float4 hc = gv[c * 32 + lane];
    float4 v = make_float4(dc * hc.x, dc * hc.y, dc * hc.z, dc * hc.w);
    float4 s = v, mn = v, mx = v;
    int e0 = g_off[c], e1 = g_off[c + 1];
    int j = e0;
    for (; j + 4 <= e1; j += 4) {
        int r0 = __ldg(&g_src[j]);
        int r1 = __ldg(&g_src[j + 1]);
        int r2 = __ldg(&g_src[j + 2]);
        int r3 = __ldg(&g_src[j + 3]);
        float d0 = __ldg(&g_dinv[r0]);
        float d1 = __ldg(&g_dinv[r1]);
        float d2 = __ldg(&g_dinv[r2]);
        float d3 = __ldg(&g_dinv[r3]);
        float4 u0 = __ldg(&gv[r0 * 32 + lane]);
        float4 u1 = __ldg(&gv[r1 * 32 + lane]);
        float4 u2 = __ldg(&gv[r2 * 32 + lane]);
        float4 u3 = __ldg(&gv[r3 * 32 + lane]);
        upd(s, mn, mx, d0, u0);
        upd(s, mn, mx, d1, u1);
        upd(s, mn, mx, d2, u2);
        upd(s, mn, mx, d3, u3);
    }
    for (; j < e1; j++) {
        int r = __ldg(&g_src[j]);
        float d = __ldg(&g_dinv[r]);
        upd(s, mn, mx, d, __ldg(&gv[r * 32 + lane]));
    }
    float rdg = 1.0f / (float)g_deg[c];
    float4* fv = (float4*)g_feat;
    int b = c * (DC / 4);
    float4 ad = make_float4(dc * s.x, dc * s.y, dc * s.z, dc * s.w);
    fv[b + lane]      = make_float4(ad.x * rdg, ad.y * rdg, ad.z * rdg, ad.w * rdg);
    fv[b + 32 + lane] = ad;
    fv[b + 64 + lane] = make_float4(dc * mn.x, dc * mn.y, dc * mn.z, dc * mn.w);
    fv[b + 96 + lane] = make_float4(dc * mx.x, dc * mx.y, dc * mx.z, dc * mx.w);
}

// ---------------- bf16 m16n8k16 3-pass GEMM, register double-buffered ----------------
// C[M,128] = A[M,K] @ B[128,K]^T; 128x128 CTA tile; 8 warps as 4x2 (32x64 each).
// acc += ah*bh + al*bh + ah*bl  (al*bl term ~2^-18, dropped)
// EPI 0: C = acc ; EPI 2: C = relu(acc + bias[n])
#define SSTRW 12   // smem row stride in uint32 words (conflict-free: g*12+tig distinct banks)

template <int K, int EPI, int ASRC, int CDST>
__global__ void __launch_bounds__(256, 2) k_mma(const float* __restrict__ Aext,
                                                const float* __restrict__ B,
                                                const float* __restrict__ bias_p) {
    const float* A = (ASRC == 0) ? Aext : (ASRC == 1 ? (const float*)g_feat
                                                     : (const float*)g_x1);
    float* C = (CDST == 0) ? g_gbuf : g_x1;

    __shared__ uint32_t Ah[128 * SSTRW], Al[128 * SSTRW];
    __shared__ uint32_t Bh[128 * SSTRW], Bl[128 * SSTRW];

    const int tid = threadIdx.x;
    const int wid = tid >> 5, lane = tid & 31;
    const int g = lane >> 2, tig = lane & 3;
    const int wr = wid >> 1, wc = wid & 1;
    const int m0 = blockIdx.x * 128;
    constexpr int NC = K / 16;

    int rowj[2], c4j[2];
    bool okA[2];
    #pragma unroll
    for (int j = 0; j < 2; j++) {
        const int idx = tid + j * 256;
        rowj[j] = idx >> 2;
        c4j[j]  = idx & 3;
        okA[j]  = (m0 + rowj[j]) < NN;
    }

    float acc[2][8][4];
    #pragma unroll
    for (int mt = 0; mt < 2; mt++)
        #pragma unroll
        for (int nt = 0; nt < 8; nt++)
            #pragma unroll
            for (int q = 0; q < 4; q++) acc[mt][nt][q] = 0.f;

    float4 avB[2], bvB[2];
    #pragma unroll
    for (int j = 0; j < 2; j++) {
        avB[j] = make_float4(0.f, 0.f, 0.f, 0.f);
        if (okA[j])
            avB[j] = *(const float4*)(A + (size_t)(m0 + rowj[j]) * K + c4j[j] * 4);
        bvB[j] = *(const float4*)(B + (size_t)rowj[j] * K + c4j[j] * 4);
    }

    #pragma unroll 1
    for (int ch = 0; ch < NC; ch++) {
        // split current buffered chunk into bf16 hi/lo, store packed pairs
        #pragma unroll
        for (int j = 0; j < 2; j++) {
            uint32_t h0, l0, h1, l1;
            const int w0 = rowj[j] * SSTRW + c4j[j] * 2;
            split2(avB[j].x, avB[j].y, h0, l0);
            split2(avB[j].z, avB[j].w, h1, l1);
            *(uint2*)&Ah[w0] = make_uint2(h0, h1);
            *(uint2*)&Al[w0] = make_uint2(l0, l1);
            split2(bvB[j].x, bvB[j].y, h0, l0);
            split2(bvB[j].z, bvB[j].w, h1, l1);
            *(uint2*)&Bh[w0] = make_uint2(h0, h1);
            *(uint2*)&Bl[w0] = make_uint2(l0, l1);
        }
        __syncthreads();

        // prefetch next chunk (latency hides under MMA phase)
        if (ch + 1 < NC) {
            const int kof = (ch + 1) * 16;
            #pragma unroll
            for (int j = 0; j < 2; j++) {
                avB[j] = make_float4(0.f, 0.f, 0.f, 0.f);
                if (okA[j])
                    avB[j] = *(const float4*)(A + (size_t)(m0 + rowj[j]) * K + kof + c4j[j] * 4);
                bvB[j] = *(const float4*)(B + (size_t)rowj[j] * K + kof + c4j[j] * 4);
            }
        }

        {
            uint32_t bb[8][2], ah[2][4], al[2][4];
            #pragma unroll
            for (int nt = 0; nt < 8; nt++) {
                const int n = wc * 64 + nt * 8 + g;
                bb[nt][0] = Bh[n * SSTRW + tig];
                bb[nt][1] = Bh[n * SSTRW + tig + 4];
            }
            #pragma unroll
            for (int mt = 0; mt < 2; mt++) {
                const int m = wr * 32 + mt * 16 + g;
                ah[mt][0] = Ah[m * SSTRW + tig];
                ah[mt][1] = Ah[(m + 8) * SSTRW + tig];
                ah[mt][2] = Ah[m * SSTRW + tig + 4];
                ah[mt][3] = Ah[(m + 8) * SSTRW + tig + 4];
            }
            // pass 1: ah*bh
            #pragma unroll
            for (int mt = 0; mt < 2; mt++)
                #pragma unroll
                for (int nt = 0; nt < 8; nt++) mma16(acc[mt][nt], ah[mt], bb[nt]);
            // pass 2: al*bh
            #pragma unroll
            for (int mt = 0; mt < 2; mt++) {
                const int m = wr * 32 + mt * 16 + g;
                al[mt][0] = Al[m * SSTRW + tig];
                al[mt][1] = Al[(m + 8) * SSTRW + tig];
                al[mt][2] = Al[m * SSTRW + tig + 4];
                al[mt][3] = Al[(m + 8) * SSTRW + tig + 4];
            }
            #pragma unroll
            for (int mt = 0; mt < 2; mt++)
                #pragma unroll
                for (int nt = 0; nt < 8; nt++) mma16(acc[mt][nt], al[mt], bb[nt]);
            // pass 3: ah*bl (reuse bb regs)
            #pragma unroll
            for (int nt = 0; nt < 8; nt++) {
                const int n = wc * 64 + nt * 8 + g;
                bb[nt][0] = Bl[n * SSTRW + tig];
                bb[nt][1] = Bl[n * SSTRW + tig + 4];
            }
            #pragma unroll
            for (int mt = 0; mt < 2; mt++)
                #pragma unroll
                for (int nt = 0; nt < 8; nt++) mma16(acc[mt][nt], ah[mt], bb[nt]);
        }
        __syncthreads();
    }

    // epilogue
    #pragma unroll
    for (int mt = 0; mt < 2; mt++) {
        const int r0 = m0 + wr * 32 + mt * 16 + g;
        const int r1 = r0 + 8;
        if (EPI == 0) {
            #pragma unroll
            for (int nt = 0; nt < 8; nt++) {
                const int col = wc * 64 + nt * 8 + tig * 2;
                if (r0 < NN)
                    *(float2*)&C[(size_t)r0 * 128 + col] =
                        make_float2(acc[mt][nt][0], acc[mt][nt][1]);
                if (r1 < NN)
                    *(float2*)&C[(size_t)r1 * 128 + col] =
                        make_float2(acc[mt][nt][2], acc[mt][nt][3]);
            }
        } else {
            #pragma unroll
            for (int nt = 0; nt < 8; nt++) {
                const int col = wc * 64 + nt * 8 + tig * 2;
                const float2 bv = *(const float2*)&bias_p[col];
                if (r0 < NN)
                    *(float2*)&C[(size_t)r0 * 128 + col] =
                        make_float2(fmaxf(acc[mt][nt][0] + bv.x, 0.f),
                                    fmaxf(acc[mt][nt][1] + bv.y, 0.f));
                if (r1 < NN)
                    *(float2*)&C[(size_t)r1 * 128 + col] =
                        make_float2(fmaxf(acc[mt][nt][2] + bv.x, 0.f),
                                    fmaxf(acc[mt][nt][3] + bv.y, 0.f));
            }
        }
    }
}

// ---------------- classifier + log_softmax: warp per node ----------------
__global__ void __launch_bounds__(256) k_out(const float* __restrict__ W,
                                             const float* __restrict__ bias,
                                             float* __restrict__ out) {
    __shared__ float ws[NCLS * 129];
    __shared__ float xs[8][128];
    __shared__ float bs[NCLS];
    int tid = threadIdx.x;
    for (int i = tid; i < NCLS * D; i += 256) {
        int c = i >> 7, k = i & 127;
        ws[c * 129 + k] = W[i];
    }
    if (tid < NCLS) bs[tid] = bias[tid];
    int w = tid >> 5, lane = tid & 31;
    int node = blockIdx.x * 8 + w;
    #pragma unroll
    for (int q = 0; q < 4; q++)
        xs[w][lane + 32 * q] = g_x1[node * D + lane + 32 * q];
    __syncthreads();

    int c2 = 32 + (lane & 7);
    float acc0 = bs[lane];
    float acc1 = bs[c2];
    #pragma unroll 8
    for (int k = 0; k < D; k++) {
        float xv = xs[w][k];
        acc0 = fmaf(xv, ws[lane * 129 + k], acc0);
        acc1 = fmaf(xv, ws[c2 * 129 + k], acc1);
    }
    bool v1 = (lane < 8);
    float m = fmaxf(acc0, v1 ? acc1 : -1e30f);
    #pragma unroll
    for (int d = 16; d; d >>= 1) m = fmaxf(m, __shfl_xor_sync(0xffffffffu, m, d));
    float s = expf(acc0 - m) + (v1 ? expf(acc1 - m) : 0.f);
    #pragma unroll
    for (int d = 16; d; d >>= 1) s += __shfl_xor_sync(0xffffffffu, s, d);
    float lse = m + logf(s);
    out[node * NCLS + lane] = acc0 - lse;
    if (v1) out[node * NCLS + 32 + lane] = acc1 - lse;
}

// ---------------- launch ----------------
extern "C" void kernel_launch(void* const* d_in, const int* in_sizes, int n_in,
                              void* d_out, int out_size) {
    (void)in_sizes; (void)n_in; (void)out_size;
    const float* x    = (const float*)d_in[0];
    const int*   ei   = (const int*)d_in[1];
    const float* W0   = (const float*)d_in[2];
    const float* C0   = (const float*)d_in[3];
    const float* b0   = (const float*)d_in[4];
    const float* W1   = (const float*)d_in[5];
    const float* C1   = (const float*)d_in[6];
    const float* b1   = (const float*)d_in[7];
    const float* Wout = (const float*)d_in[8];
    const float* bout = (const float*)d_in[9];
    float* out = (float*)d_out;

    const int EB = (NE + 255) / 256;

    // build (first 3) then lin-GEMM L0 as launch #4 so ncu's fixed window
    // lands on the GEMM kernel (round-over-round comparable).
    k_init  <<<SCAN_NB, 256>>>();
    k_count <<<EB, 256>>>(ei);
    k_scan_a<<<SCAN_NB, 256>>>();
    k_mma<128, 0, 0, 0><<<NT, 256>>>(x, W0, nullptr);      // h0 = x @ W0^T  [PROFILED]
    k_scan_b<<<1, 256>>>();
    k_scan_c<<<SCAN_NB, 256>>>();
    k_fill  <<<EB, 256>>>(ei);

    // layer 0 aggregate + combine
    k_aggregate<<<NN / 8, 256>>>();
    k_mma<512, 2, 1, 1><<<NT, 256>>>(nullptr, C0, b0);

    // layer 1
    k_mma<128, 0, 2, 0><<<NT, 256>>>(nullptr, W1, nullptr);
    k_aggregate<<<NN / 8, 256>>>();
    k_mma<512, 2, 1, 1><<<NT, 256>>>(nullptr, C1, b1);

    k_out<<<NN / 8, 256>>>(Wout, bout, out);
}